// round 14
// baseline (speedup 1.0000x reference)
#include <cuda_runtime.h>
#include <math.h>
#include <stdint.h>

// Problem constants
#define BN   4096
#define TN   512
#define ZD   64
#define OU   128
#define BERT 768
#define TOUT 513

// Scratch (device globals: no allocation allowed)
__device__ float gZaug[BN * ZD];
__device__ float gPartial[BN];

// tanh(x) = 1 - 2/(exp2(2x*log2e)+1). HW-validated (R3/R6/R9/R11).
__device__ __forceinline__ float fast_tanh(float x) {
    float e;
    asm("ex2.approx.f32 %0, %1;" : "=f"(e) : "f"(x * 2.8853900817779268f));
    return 1.0f - __fdividef(2.0f, e + 1.0f);
}

__device__ __forceinline__ uint32_t smem_u32(const void* p) {
    uint32_t a;
    asm("{ .reg .u64 t; cvta.to.shared.u64 t, %1; cvt.u32.u64 %0, t; }"
        : "=r"(a) : "l"(p));
    return a;
}

__device__ __forceinline__ void ldsm4(uint32_t& r0, uint32_t& r1,
                                      uint32_t& r2, uint32_t& r3, uint32_t addr) {
    asm volatile("ldmatrix.sync.aligned.m8n8.x4.shared.b16 {%0,%1,%2,%3}, [%4];"
                 : "=r"(r0), "=r"(r1), "=r"(r2), "=r"(r3) : "r"(addr));
}

__device__ __forceinline__ void mma_bf16(float c[4], uint32_t a0, uint32_t a1,
                                         uint32_t a2, uint32_t a3,
                                         uint32_t b0, uint32_t b1) {
    asm volatile("mma.sync.aligned.m16n8k16.row.col.f32.bf16.bf16.f32 "
                 "{%0,%1,%2,%3}, {%4,%5,%6,%7}, {%8,%9}, {%0,%1,%2,%3};"
                 : "+f"(c[0]), "+f"(c[1]), "+f"(c[2]), "+f"(c[3])
                 : "r"(a0), "r"(a1), "r"(a2), "r"(a3), "r"(b0), "r"(b1));
}

// fp32 pair -> bf16x2 hi (truncation) + bf16x2 lo (exact residual, truncated)
__device__ __forceinline__ void pack2(float v0, float v1, uint32_t& h, uint32_t& l) {
    uint32_t u0 = __float_as_uint(v0), u1 = __float_as_uint(v1);
    h = __byte_perm(u0, u1, 0x7632);
    float l0 = v0 - __uint_as_float(u0 & 0xFFFF0000u);
    float l1 = v1 - __uint_as_float(u1 & 0xFFFF0000u);
    l = __byte_perm(__float_as_uint(l0), __float_as_uint(l1), 0x7632);
}

// ---------------------------------------------------------------------------
// Phase A: warp-per-row (unchanged, validated ~110us)
// ---------------------------------------------------------------------------
__global__ __launch_bounds__(256) void phaseA_kernel(
    const float* __restrict__ bert, const float* __restrict__ eps,
    const float* __restrict__ projW, const float* __restrict__ projB,
    const float* __restrict__ lnG, const float* __restrict__ lnB,
    const float* __restrict__ lns,
    const float* __restrict__ dW1, const float* __restrict__ db1,
    const float* __restrict__ dW2, const float* __restrict__ db2,
    const float* __restrict__ decW, const float* __restrict__ decB,
    float* __restrict__ outPd, float* __restrict__ outSl)
{
    const unsigned FULL = 0xffffffffu;
    int warp = (blockIdx.x * blockDim.x + threadIdx.x) >> 5;
    int l = threadIdx.x & 31;
    if (warp >= BN) return;
    const int r = warp;
    const int c = 2 * l;

    const float* brow = bert + (size_t)r * BERT;
    float hx = 0.f, hy = 0.f;
    #pragma unroll 4
    for (int k = 0; k < BERT; k++) {
        float bv = __ldg(brow + k);
        float2 wv = *(const float2*)(projW + k * ZD + c);
        hx = fmaf(bv, wv.x, hx);
        hy = fmaf(bv, wv.y, hy);
    }
    hx += projB[c]; hy += projB[c + 1];

    float s = hx + hy;
    #pragma unroll
    for (int o = 16; o; o >>= 1) s += __shfl_xor_sync(FULL, s, o);
    float mu = s * (1.0f / 64.0f);
    float d0 = hx - mu, d1 = hy - mu;
    float ss = d0 * d0 + d1 * d1;
    #pragma unroll
    for (int o = 16; o; o >>= 1) ss += __shfl_xor_sync(FULL, ss, o);
    float var = ss * (1.0f / 64.0f);
    float rs = rsqrtf(var + 1e-5f);
    float zc0 = d0 * rs * lnG[c]     + lnB[c];
    float zc1 = d1 * rs * lnG[c + 1] + lnB[c + 1];

    float sigma = log1pf(expf(lns[0]));
    float zn0 = zc0 + sigma * eps[(size_t)r * ZD + c];
    float zn1 = zc1 + sigma * eps[(size_t)r * ZD + c + 1];

    int j0 = 4 * l;
    float4 a = *(const float4*)(db1 + j0);
    #pragma unroll 4
    for (int k2 = 0; k2 < 32; k2++) {
        float zva = __shfl_sync(FULL, zn0, k2);
        float zvb = __shfl_sync(FULL, zn1, k2);
        int k = 2 * k2;
        float4 w = *(const float4*)(dW1 + k * OU + j0);
        a.x = fmaf(zva, w.x, a.x); a.y = fmaf(zva, w.y, a.y);
        a.z = fmaf(zva, w.z, a.z); a.w = fmaf(zva, w.w, a.w);
        w = *(const float4*)(dW1 + (k + 1) * OU + j0);
        a.x = fmaf(zvb, w.x, a.x); a.y = fmaf(zvb, w.y, a.y);
        a.z = fmaf(zvb, w.z, a.z); a.w = fmaf(zvb, w.w, a.w);
    }
    a.x = a.x / (1.f + expf(-a.x));
    a.y = a.y / (1.f + expf(-a.y));
    a.z = a.z / (1.f + expf(-a.z));
    a.w = a.w / (1.f + expf(-a.w));

    float za0 = db2[c], za1 = db2[c + 1];
    float a1v[4] = {a.x, a.y, a.z, a.w};
    #pragma unroll 2
    for (int k4 = 0; k4 < 32; k4++) {
        #pragma unroll
        for (int j = 0; j < 4; j++) {
            float hv = __shfl_sync(FULL, a1v[j], k4);
            int k = 4 * k4 + j;
            float2 w = *(const float2*)(dW2 + k * ZD + c);
            za0 = fmaf(hv, w.x, za0);
            za1 = fmaf(hv, w.y, za1);
        }
    }

    float dd = (za0 - zc0) * (za0 - zc0) + (za1 - zc1) * (za1 - zc1);
    #pragma unroll
    for (int o = 16; o; o >>= 1) dd += __shfl_xor_sync(FULL, dd, o);
    if (l == 0) gPartial[r] = dd;

    *(float2*)(gZaug + (size_t)r * ZD + c) = make_float2(za0, za1);

    float pd = za0 * decW[c * 2 + 0] + za1 * decW[(c + 1) * 2 + 0];
    float sl = za0 * decW[c * 2 + 1] + za1 * decW[(c + 1) * 2 + 1];
    #pragma unroll
    for (int o = 16; o; o >>= 1) {
        pd += __shfl_xor_sync(FULL, pd, o);
        sl += __shfl_xor_sync(FULL, sl, o);
    }
    if (l == 0) {
        outPd[(size_t)r * TOUT] = pd + decB[0];
        outSl[(size_t)r * TOUT] = sl + decB[1];
    }
}

__global__ void reduceDiff_kernel(float* __restrict__ outDiff)
{
    __shared__ float sh[256];
    float s = 0.f;
    for (int i = threadIdx.x; i < BN; i += 256) s += gPartial[i];
    sh[threadIdx.x] = s;
    __syncthreads();
    for (int step = 128; step; step >>= 1) {
        if (threadIdx.x < step) sh[threadIdx.x] += sh[threadIdx.x + step];
        __syncthreads();
    }
    if (threadIdx.x == 0) outDiff[0] = sh[0] * (1.0f / ((float)BN * (float)ZD));
}

// ---------------------------------------------------------------------------
// SMEM layout. Weights transposed n-major, stride +16B pad (conflict-free).
// h tiles: row-major [16 rows][128 bf16], stride 272B, hi then lo (+4352B),
// one tile per 16-row group (2 per CTA).
// ---------------------------------------------------------------------------
#define S_W1 144
#define S_W2 272
#define S_W3 272
#define S_H  272
#define H_LO 4352
#define H_PAIR 8704
#define OFF_W1H 0
#define OFF_W1L (OFF_W1H + 128 * S_W1)
#define OFF_W2H (OFF_W1L + 128 * S_W1)
#define OFF_W2L (OFF_W2H + 128 * S_W2)
#define OFF_W3H (OFF_W2L + 128 * S_W2)
#define OFF_W3L (OFF_W3H + 64 * S_W3)
#define OFF_B1  (OFF_W3L + 64 * S_W3)
#define OFF_B2  (OFF_B1 + 512)
#define OFF_B3  (OFF_B2 + 512)
#define OFF_D0  (OFF_B3 + 256)
#define OFF_D1  (OFF_D0 + 256)
#define OFF_H1  (OFF_D1 + 256)                 // 2 groups x 8704
#define OFF_H2  (OFF_H1 + 2 * H_PAIR)
#define OFF_XF  (OFF_H2 + 2 * H_PAIR)          // f: [8][256] f32
#define SMEM_USED (OFF_XF + 8192)              // 186112

// A from smem via ldmatrix
template<int NKC, int NJ, int STRIDE>
__device__ __forceinline__ void gemm_pass_sA(float D[][4], uint32_t aBase,
                                             uint32_t bBase) {
    #pragma unroll
    for (int kc = 0; kc < NKC; kc++) {
        uint32_t a0, a1, a2, a3;
        ldsm4(a0, a1, a2, a3, aBase + kc * 32);
        #pragma unroll
        for (int j = 0; j < NJ; j += 2) {
            uint32_t b0, b1, b2, b3;
            ldsm4(b0, b1, b2, b3, bBase + j * 8 * STRIDE + kc * 32);
            mma_bf16(D[j],     a0, a1, a2, a3, b0, b1);
            mma_bf16(D[j + 1], a0, a1, a2, a3, b2, b3);
        }
    }
}

// A from registers (GEMM1: z fragments)
template<int NKC, int NJ, int STRIDE>
__device__ __forceinline__ void gemm_pass_rA(float D[][4], const uint32_t* a,
                                             uint32_t bBase) {
    #pragma unroll
    for (int kc = 0; kc < NKC; kc++) {
        #pragma unroll
        for (int j = 0; j < NJ; j += 2) {
            uint32_t b0, b1, b2, b3;
            ldsm4(b0, b1, b2, b3, bBase + j * 8 * STRIDE + kc * 32);
            mma_bf16(D[j],     a[4*kc+0], a[4*kc+1], a[4*kc+2], a[4*kc+3], b0, b1);
            mma_bf16(D[j + 1], a[4*kc+0], a[4*kc+1], a[4*kc+2], a[4*kc+3], b2, b3);
        }
    }
}

template<int NJ>
__device__ __forceinline__ void init_bias(float D[][4], const char* sB, int tq) {
    #pragma unroll
    for (int j = 0; j < NJ; j++) {
        float2 b = *(const float2*)(sB + (8 * j + 2 * tq) * 4);
        D[j][0] = b.x; D[j][1] = b.y; D[j][2] = b.x; D[j][3] = b.y;
    }
}

// tanh(D)+pack -> store own cols into h tile (conflict-free)
template<int NJ>
__device__ __forceinline__ void epi_store_h(float D[][4], char* htile,
                                            int g, int tq, int colBase) {
    #pragma unroll
    for (int j = 0; j < NJ; j++) {
        float v0 = fast_tanh(D[j][0]);
        float v1 = fast_tanh(D[j][1]);
        float v2 = fast_tanh(D[j][2]);
        float v3 = fast_tanh(D[j][3]);
        uint32_t h0, l0, h1, l1;
        pack2(v0, v1, h0, l0);
        pack2(v2, v3, h1, l1);
        int colB = (colBase + 8 * j + 2 * tq) * 2;
        *(uint32_t*)(htile + g * S_H + colB)              = h0;
        *(uint32_t*)(htile + g * S_H + colB + H_LO)       = l0;
        *(uint32_t*)(htile + (g + 8) * S_H + colB)        = h1;
        *(uint32_t*)(htile + (g + 8) * S_H + colB + H_LO) = l1;
    }
}

// ---------------------------------------------------------------------------
// Phase B: mma.sync ODE scan, 4-way N-split.
// 128 CTAs x 256 threads (8 warps = 2 row-groups x 4 N-quarter warps).
// Warp q of a group computes output cols [32q,32q+32) (GEMM3: [16q,16q+16)).
// h activations exchanged through smem tiles via ldmatrix. z fp32,
// replicated in all 4 warps of a group. 2 warps/SMSP -> latency hiding.
// ---------------------------------------------------------------------------
__global__ __launch_bounds__(256, 1) void ode_mma_kernel(
    const float* __restrict__ oW1, const float* __restrict__ ob1,
    const float* __restrict__ oW2, const float* __restrict__ ob2,
    const float* __restrict__ oW3, const float* __restrict__ ob3,
    const float* __restrict__ decW, const float* __restrict__ decB,
    float* __restrict__ outPd, float* __restrict__ outSl)
{
    extern __shared__ char smraw[];
    uint32_t sb0 = smem_u32(smraw);
    uint32_t sbase = (sb0 + 1023) & ~1023u;
    char* sm = smraw + (sbase - sb0);
    const int tid = threadIdx.x;

    // ---- Fill transposed hi/lo weight tiles (one-time) ----
    for (int idx = tid; idx < ZD * OU; idx += 256) {           // W1 [64k][128n]
        int k = idx >> 7, n = idx & 127;
        float v = oW1[idx];
        uint32_t u = __float_as_uint(v);
        float lo = v - __uint_as_float(u & 0xFFFF0000u);
        *(uint16_t*)(sm + OFF_W1H + n * S_W1 + k * 2) = (uint16_t)(u >> 16);
        *(uint16_t*)(sm + OFF_W1L + n * S_W1 + k * 2) = (uint16_t)(__float_as_uint(lo) >> 16);
    }
    for (int idx = tid; idx < OU * OU; idx += 256) {           // W2 [128][128]
        int k = idx >> 7, n = idx & 127;
        float v = oW2[idx];
        uint32_t u = __float_as_uint(v);
        float lo = v - __uint_as_float(u & 0xFFFF0000u);
        *(uint16_t*)(sm + OFF_W2H + n * S_W2 + k * 2) = (uint16_t)(u >> 16);
        *(uint16_t*)(sm + OFF_W2L + n * S_W2 + k * 2) = (uint16_t)(__float_as_uint(lo) >> 16);
    }
    for (int idx = tid; idx < OU * ZD; idx += 256) {           // W3 [128k][64n]
        int k = idx >> 6, n = idx & 63;
        float v = oW3[idx];
        uint32_t u = __float_as_uint(v);
        float lo = v - __uint_as_float(u & 0xFFFF0000u);
        *(uint16_t*)(sm + OFF_W3H + n * S_W3 + k * 2) = (uint16_t)(u >> 16);
        *(uint16_t*)(sm + OFF_W3L + n * S_W3 + k * 2) = (uint16_t)(__float_as_uint(lo) >> 16);
    }
    if (tid < OU) {
        ((float*)(sm + OFF_B1))[tid] = ob1[tid];
        ((float*)(sm + OFF_B2))[tid] = ob2[tid];
    }
    if (tid < ZD) {
        ((float*)(sm + OFF_B3))[tid] = ob3[tid];
        ((float*)(sm + OFF_D0))[tid] = decW[2 * tid];
        ((float*)(sm + OFF_D1))[tid] = decW[2 * tid + 1];
    }
    __syncthreads();

    const int wi = tid >> 5, l = tid & 31;
    const int q = wi & 3;                     // N-quarter
    const int rg = wi >> 2;                   // row-group (0/1)
    const int base = blockIdx.x * 32 + rg * 16;
    const int g = l >> 2, tq = l & 3;
    const int laneRow = l & 7, mi = l >> 3;

    // B-side ldmatrix lane addresses
    const int jo = mi >> 1, hf = mi & 1;
    const uint32_t aW1H = sbase + OFF_W1H + (uint32_t)((32 * q + jo * 8 + laneRow) * S_W1 + hf * 16);
    const uint32_t aW1L = aW1H + (uint32_t)(OFF_W1L - OFF_W1H);
    const uint32_t aW2H = sbase + OFF_W2H + (uint32_t)((32 * q + jo * 8 + laneRow) * S_W2 + hf * 16);
    const uint32_t aW2L = aW2H + (uint32_t)(OFF_W2L - OFF_W2H);
    const uint32_t aW3H = sbase + OFF_W3H + (uint32_t)((16 * q + jo * 8 + laneRow) * S_W3 + hf * 16);
    const uint32_t aW3L = aW3H + (uint32_t)(OFF_W3L - OFF_W3H);

    // A-side ldmatrix lane addresses into group h tile
    const uint32_t aoff = (uint32_t)((laneRow + 8 * (mi & 1)) * S_H + (mi >> 1) * 16);
    const uint32_t aH1 = sbase + OFF_H1 + (uint32_t)(rg * H_PAIR) + aoff;
    const uint32_t aH1L = aH1 + H_LO;
    const uint32_t aH2 = sbase + OFF_H2 + (uint32_t)(rg * H_PAIR) + aoff;
    const uint32_t aH2L = aH2 + H_LO;
    char* h1w = sm + OFF_H1 + rg * H_PAIR;
    char* h2w = sm + OFF_H2 + rg * H_PAIR;
    float* fbuf = (float*)(sm + OFF_XF);

    // fp32 z state (full 64 cols, replicated x4 per group), D-frag layout
    float z[8][4];
    #pragma unroll
    for (int j = 0; j < 8; j++) {
        float2 p = *(const float2*)(gZaug + (size_t)(base + g) * ZD + 8 * j + 2 * tq);
        float2 qv = *(const float2*)(gZaug + (size_t)(base + g + 8) * ZD + 8 * j + 2 * tq);
        z[j][0] = p.x; z[j][1] = p.y; z[j][2] = qv.x; z[j][3] = qv.y;
    }

    const float dt = 1.0f / (float)TN;
    const float db0 = decB[0], db1v = decB[1];
    const unsigned FULL = 0xffffffffu;

    for (int t = 0; t < TN; t++) {
        // ===== GEMM1: D = z @ W1 + b1 (K=64 -> own 32 cols) =====
        float D[4][4];
        init_bias<4>(D, sm + OFF_B1 + 32 * q * 4, tq);
        {
            uint32_t zah[16], zal[16];
            #pragma unroll
            for (int kc = 0; kc < 4; kc++) {
                pack2(z[2*kc][0],   z[2*kc][1],   zah[4*kc+0], zal[4*kc+0]);
                pack2(z[2*kc][2],   z[2*kc][3],   zah[4*kc+1], zal[4*kc+1]);
                pack2(z[2*kc+1][0], z[2*kc+1][1], zah[4*kc+2], zal[4*kc+2]);
                pack2(z[2*kc+1][2], z[2*kc+1][3], zah[4*kc+3], zal[4*kc+3]);
            }
            gemm_pass_rA<4, 4, S_W1>(D, zah, aW1H);
            gemm_pass_rA<4, 4, S_W1>(D, zah, aW1L);
            gemm_pass_rA<4, 4, S_W1>(D, zal, aW1H);
        }
        epi_store_h<4>(D, h1w, g, tq, 32 * q);
        __syncthreads();

        // ===== GEMM2: D = h1 @ W2 + b2 (K=128 -> own 32 cols) =====
        init_bias<4>(D, sm + OFF_B2 + 32 * q * 4, tq);
        gemm_pass_sA<8, 4, S_W2>(D, aH1,  aW2H);
        gemm_pass_sA<8, 4, S_W2>(D, aH1,  aW2L);
        gemm_pass_sA<8, 4, S_W2>(D, aH1L, aW2H);
        epi_store_h<4>(D, h2w, g, tq, 32 * q);
        __syncthreads();

        // ===== GEMM3: D3 = h2 @ W3 + b3 (K=128 -> own 16 cols) =====
        float D3[2][4];
        init_bias<2>(D3, sm + OFF_B3 + 16 * q * 4, tq);
        gemm_pass_sA<8, 2, S_W3>(D3, aH2,  aW3H);
        gemm_pass_sA<8, 2, S_W3>(D3, aH2,  aW3L);
        gemm_pass_sA<8, 2, S_W3>(D3, aH2L, aW3H);

        // f exchange: transposed layout [i][tid] -> conflict-free
        #pragma unroll
        for (int jj = 0; jj < 2; jj++) {
            fbuf[(4*jj + 0) * 256 + tid] = D3[jj][0];
            fbuf[(4*jj + 1) * 256 + tid] = D3[jj][1];
            fbuf[(4*jj + 2) * 256 + tid] = D3[jj][2];
            fbuf[(4*jj + 3) * 256 + tid] = D3[jj][3];
        }
        __syncthreads();

        // ===== z update (full, replicated), decode, store =====
        float pdA = 0.f, pdB = 0.f, slA = 0.f, slB = 0.f;
        #pragma unroll
        for (int j = 0; j < 8; j++) {
            int qo = j >> 1, jj = j & 1;
            float f0, f1, f2, f3;
            if (qo == q) {
                f0 = D3[jj][0]; f1 = D3[jj][1]; f2 = D3[jj][2]; f3 = D3[jj][3];
            } else {
                int ptid = tid + (qo - q) * 32;   // partner warp, same lane/group
                f0 = fbuf[(4*jj + 0) * 256 + ptid];
                f1 = fbuf[(4*jj + 1) * 256 + ptid];
                f2 = fbuf[(4*jj + 2) * 256 + ptid];
                f3 = fbuf[(4*jj + 3) * 256 + ptid];
            }
            z[j][0] = fmaf(dt, f0, z[j][0]);
            z[j][1] = fmaf(dt, f1, z[j][1]);
            z[j][2] = fmaf(dt, f2, z[j][2]);
            z[j][3] = fmaf(dt, f3, z[j][3]);
            float2 d0 = *(const float2*)(sm + OFF_D0 + (8 * j + 2 * tq) * 4);
            float2 d1 = *(const float2*)(sm + OFF_D1 + (8 * j + 2 * tq) * 4);
            pdA += z[j][0] * d0.x + z[j][1] * d0.y;
            pdB += z[j][2] * d0.x + z[j][3] * d0.y;
            slA += z[j][0] * d1.x + z[j][1] * d1.y;
            slB += z[j][2] * d1.x + z[j][3] * d1.y;
        }
        pdA += __shfl_xor_sync(FULL, pdA, 1); pdA += __shfl_xor_sync(FULL, pdA, 2);
        pdB += __shfl_xor_sync(FULL, pdB, 1); pdB += __shfl_xor_sync(FULL, pdB, 2);
        slA += __shfl_xor_sync(FULL, slA, 1); slA += __shfl_xor_sync(FULL, slA, 2);
        slB += __shfl_xor_sync(FULL, slB, 1); slB += __shfl_xor_sync(FULL, slB, 2);
        if (q == 0 && tq == 0) {
            size_t r0 = (size_t)(base + g), r1 = r0 + 8;
            outPd[r0 * TOUT + t + 1] = pdA + db0;
            outSl[r0 * TOUT + t + 1] = slA + db1v;
            outPd[r1 * TOUT + t + 1] = pdB + db0;
            outSl[r1 * TOUT + t + 1] = slB + db1v;
        }
    }
}

// ---------------------------------------------------------------------------
// Launch
// ---------------------------------------------------------------------------
extern "C" void kernel_launch(void* const* d_in, const int* in_sizes, int n_in,
                              void* d_out, int out_size)
{
    const float* bert  = (const float*)d_in[0];
    const float* eps   = (const float*)d_in[3];
    const float* projW = (const float*)d_in[4];
    const float* projB = (const float*)d_in[5];
    const float* lnG   = (const float*)d_in[6];
    const float* lnB   = (const float*)d_in[7];
    const float* lns   = (const float*)d_in[8];
    const float* dW1   = (const float*)d_in[9];
    const float* db1   = (const float*)d_in[10];
    const float* dW2   = (const float*)d_in[11];
    const float* db2   = (const float*)d_in[12];
    const float* oW1   = (const float*)d_in[13];
    const float* ob1   = (const float*)d_in[14];
    const float* oW2   = (const float*)d_in[15];
    const float* ob2   = (const float*)d_in[16];
    const float* oW3   = (const float*)d_in[17];
    const float* ob3   = (const float*)d_in[18];
    const float* decW  = (const float*)d_in[19];
    const float* decB  = (const float*)d_in[20];

    float* out    = (float*)d_out;
    float* outPd  = out;
    float* outSl  = out + (size_t)BN * TOUT;
    float* outDif = out + 2 * (size_t)BN * TOUT;

    phaseA_kernel<<<512, 256>>>(bert, eps, projW, projB, lnG, lnB, lns,
                                dW1, db1, dW2, db2, decW, decB, outPd, outSl);
    reduceDiff_kernel<<<1, 256>>>(outDif);

    int smemBytes = 1024 + SMEM_USED;
    cudaFuncSetAttribute(ode_mma_kernel, cudaFuncAttributeMaxDynamicSharedMemorySize,
                         smemBytes);
    ode_mma_kernel<<<BN / 32, 256, smemBytes>>>(oW1, ob1, oW2, ob2, oW3, ob3,
                                                decW, decB, outPd, outSl);
}

// round 15
// speedup vs baseline: 1.3788x; 1.3788x over previous
#include <cuda_runtime.h>
#include <cuda_fp16.h>
#include <math.h>
#include <stdint.h>

// Problem constants
#define BN   4096
#define TN   512
#define ZD   64
#define OU   128
#define BERT 768
#define TOUT 513
#define INV2048 4.8828125e-4f

// Scratch (device globals: no allocation allowed)
__device__ float gZaug[BN * ZD];
__device__ float gPartial[BN];

// tanh(x) = 1 - 2/(exp2(2x*log2e)+1). HW-validated (R3/R6/R9/R11).
__device__ __forceinline__ float fast_tanh(float x) {
    float e;
    asm("ex2.approx.f32 %0, %1;" : "=f"(e) : "f"(x * 2.8853900817779268f));
    return 1.0f - __fdividef(2.0f, e + 1.0f);
}

__device__ __forceinline__ uint32_t smem_u32(const void* p) {
    uint32_t a;
    asm("{ .reg .u64 t; cvta.to.shared.u64 t, %1; cvt.u32.u64 %0, t; }"
        : "=r"(a) : "l"(p));
    return a;
}

__device__ __forceinline__ void ldsm4(uint32_t& r0, uint32_t& r1,
                                      uint32_t& r2, uint32_t& r3, uint32_t addr) {
    asm volatile("ldmatrix.sync.aligned.m8n8.x4.shared.b16 {%0,%1,%2,%3}, [%4];"
                 : "=r"(r0), "=r"(r1), "=r"(r2), "=r"(r3) : "r"(addr));
}

__device__ __forceinline__ void mma_f16(float c[4], uint32_t a0, uint32_t a1,
                                        uint32_t a2, uint32_t a3,
                                        uint32_t b0, uint32_t b1) {
    asm volatile("mma.sync.aligned.m16n8k16.row.col.f32.f16.f16.f32 "
                 "{%0,%1,%2,%3}, {%4,%5,%6,%7}, {%8,%9}, {%0,%1,%2,%3};"
                 : "+f"(c[0]), "+f"(c[1]), "+f"(c[2]), "+f"(c[3])
                 : "r"(a0), "r"(a1), "r"(a2), "r"(a3), "r"(b0), "r"(b1));
}

// pack two fp32 -> fp16x2 (v0 low, v1 high), round-to-nearest
__device__ __forceinline__ uint32_t packh2(float v0, float v1) {
    uint32_t r;
    asm("cvt.rn.f16x2.f32 %0, %1, %2;" : "=r"(r) : "f"(v1), "f"(v0));
    return r;
}

// ---------------------------------------------------------------------------
// Phase A: warp-per-row (unchanged, validated ~110us)
// ---------------------------------------------------------------------------
__global__ __launch_bounds__(256) void phaseA_kernel(
    const float* __restrict__ bert, const float* __restrict__ eps,
    const float* __restrict__ projW, const float* __restrict__ projB,
    const float* __restrict__ lnG, const float* __restrict__ lnB,
    const float* __restrict__ lns,
    const float* __restrict__ dW1, const float* __restrict__ db1,
    const float* __restrict__ dW2, const float* __restrict__ db2,
    const float* __restrict__ decW, const float* __restrict__ decB,
    float* __restrict__ outPd, float* __restrict__ outSl)
{
    const unsigned FULL = 0xffffffffu;
    int warp = (blockIdx.x * blockDim.x + threadIdx.x) >> 5;
    int l = threadIdx.x & 31;
    if (warp >= BN) return;
    const int r = warp;
    const int c = 2 * l;

    const float* brow = bert + (size_t)r * BERT;
    float hx = 0.f, hy = 0.f;
    #pragma unroll 4
    for (int k = 0; k < BERT; k++) {
        float bv = __ldg(brow + k);
        float2 wv = *(const float2*)(projW + k * ZD + c);
        hx = fmaf(bv, wv.x, hx);
        hy = fmaf(bv, wv.y, hy);
    }
    hx += projB[c]; hy += projB[c + 1];

    float s = hx + hy;
    #pragma unroll
    for (int o = 16; o; o >>= 1) s += __shfl_xor_sync(FULL, s, o);
    float mu = s * (1.0f / 64.0f);
    float d0 = hx - mu, d1 = hy - mu;
    float ss = d0 * d0 + d1 * d1;
    #pragma unroll
    for (int o = 16; o; o >>= 1) ss += __shfl_xor_sync(FULL, ss, o);
    float var = ss * (1.0f / 64.0f);
    float rs = rsqrtf(var + 1e-5f);
    float zc0 = d0 * rs * lnG[c]     + lnB[c];
    float zc1 = d1 * rs * lnG[c + 1] + lnB[c + 1];

    float sigma = log1pf(expf(lns[0]));
    float zn0 = zc0 + sigma * eps[(size_t)r * ZD + c];
    float zn1 = zc1 + sigma * eps[(size_t)r * ZD + c + 1];

    int j0 = 4 * l;
    float4 a = *(const float4*)(db1 + j0);
    #pragma unroll 4
    for (int k2 = 0; k2 < 32; k2++) {
        float zva = __shfl_sync(FULL, zn0, k2);
        float zvb = __shfl_sync(FULL, zn1, k2);
        int k = 2 * k2;
        float4 w = *(const float4*)(dW1 + k * OU + j0);
        a.x = fmaf(zva, w.x, a.x); a.y = fmaf(zva, w.y, a.y);
        a.z = fmaf(zva, w.z, a.z); a.w = fmaf(zva, w.w, a.w);
        w = *(const float4*)(dW1 + (k + 1) * OU + j0);
        a.x = fmaf(zvb, w.x, a.x); a.y = fmaf(zvb, w.y, a.y);
        a.z = fmaf(zvb, w.z, a.z); a.w = fmaf(zvb, w.w, a.w);
    }
    a.x = a.x / (1.f + expf(-a.x));
    a.y = a.y / (1.f + expf(-a.y));
    a.z = a.z / (1.f + expf(-a.z));
    a.w = a.w / (1.f + expf(-a.w));

    float za0 = db2[c], za1 = db2[c + 1];
    float a1v[4] = {a.x, a.y, a.z, a.w};
    #pragma unroll 2
    for (int k4 = 0; k4 < 32; k4++) {
        #pragma unroll
        for (int j = 0; j < 4; j++) {
            float hv = __shfl_sync(FULL, a1v[j], k4);
            int k = 4 * k4 + j;
            float2 w = *(const float2*)(dW2 + k * ZD + c);
            za0 = fmaf(hv, w.x, za0);
            za1 = fmaf(hv, w.y, za1);
        }
    }

    float dd = (za0 - zc0) * (za0 - zc0) + (za1 - zc1) * (za1 - zc1);
    #pragma unroll
    for (int o = 16; o; o >>= 1) dd += __shfl_xor_sync(FULL, dd, o);
    if (l == 0) gPartial[r] = dd;

    *(float2*)(gZaug + (size_t)r * ZD + c) = make_float2(za0, za1);

    float pd = za0 * decW[c * 2 + 0] + za1 * decW[(c + 1) * 2 + 0];
    float sl = za0 * decW[c * 2 + 1] + za1 * decW[(c + 1) * 2 + 1];
    #pragma unroll
    for (int o = 16; o; o >>= 1) {
        pd += __shfl_xor_sync(FULL, pd, o);
        sl += __shfl_xor_sync(FULL, sl, o);
    }
    if (l == 0) {
        outPd[(size_t)r * TOUT] = pd + decB[0];
        outSl[(size_t)r * TOUT] = sl + decB[1];
    }
}

__global__ void reduceDiff_kernel(float* __restrict__ outDiff)
{
    __shared__ float sh[256];
    float s = 0.f;
    for (int i = threadIdx.x; i < BN; i += 256) s += gPartial[i];
    sh[threadIdx.x] = s;
    __syncthreads();
    for (int step = 128; step; step >>= 1) {
        if (threadIdx.x < step) sh[threadIdx.x] += sh[threadIdx.x + step];
        __syncthreads();
    }
    if (threadIdx.x == 0) outDiff[0] = sh[0] * (1.0f / ((float)BN * (float)ZD));
}

// ---------------------------------------------------------------------------
// SMEM layout. Weights fp16, transposed n-major, stride +16B pad.
// Wl stored scaled by 2048 (normalized); epilogue divides back.
// h tiles: fp16 hi only, [16 rows][128], stride 272B, per 16-row pair.
// ---------------------------------------------------------------------------
#define S_W1 144
#define S_W2 272
#define S_W3 272
#define S_H  272
#define H_GRP 4352
#define OFF_W1H 0
#define OFF_W1L (OFF_W1H + 128 * S_W1)
#define OFF_W2H (OFF_W1L + 128 * S_W1)
#define OFF_W2L (OFF_W2H + 128 * S_W2)
#define OFF_W3H (OFF_W2L + 128 * S_W2)
#define OFF_W3L (OFF_W3H + 64 * S_W3)
#define OFF_B1  (OFF_W3L + 64 * S_W3)          // 141312
#define OFF_B2  (OFF_B1 + 512)
#define OFF_B3  (OFF_B2 + 512)
#define OFF_D0  (OFF_B3 + 256)
#define OFF_D1  (OFF_D0 + 256)
#define OFF_H1  (OFF_D1 + 256)                 // 142848: 2 pairs x 4352
#define OFF_H2  (OFF_H1 + 2 * H_GRP)           // 151552
#define OFF_XF  (OFF_H2 + 2 * H_GRP)           // 160256: f [16][128] f32
#define SMEM_USED (OFF_XF + 8192)              // 168448

// 2-pass GEMM, A from smem via ldmatrix: Dh += A*Wh, Dl += A*Wl'
template<int NKC, int NJ, int STRIDE>
__device__ __forceinline__ void gemm2p_sA(float Dh[][4], float Dl[][4],
                                          uint32_t aBase, uint32_t bhBase,
                                          uint32_t blBase) {
    #pragma unroll
    for (int kc = 0; kc < NKC; kc++) {
        uint32_t a0, a1, a2, a3;
        ldsm4(a0, a1, a2, a3, aBase + kc * 32);
        #pragma unroll
        for (int j = 0; j < NJ; j += 2) {
            uint32_t b0, b1, b2, b3;
            ldsm4(b0, b1, b2, b3, bhBase + j * 8 * STRIDE + kc * 32);
            mma_f16(Dh[j],     a0, a1, a2, a3, b0, b1);
            mma_f16(Dh[j + 1], a0, a1, a2, a3, b2, b3);
            ldsm4(b0, b1, b2, b3, blBase + j * 8 * STRIDE + kc * 32);
            mma_f16(Dl[j],     a0, a1, a2, a3, b0, b1);
            mma_f16(Dl[j + 1], a0, a1, a2, a3, b2, b3);
        }
    }
}

// 2-pass GEMM, A from registers (GEMM1: z fragments)
template<int NKC, int NJ, int STRIDE>
__device__ __forceinline__ void gemm2p_rA(float Dh[][4], float Dl[][4],
                                          const uint32_t* a, uint32_t bhBase,
                                          uint32_t blBase) {
    #pragma unroll
    for (int kc = 0; kc < NKC; kc++) {
        #pragma unroll
        for (int j = 0; j < NJ; j += 2) {
            uint32_t b0, b1, b2, b3;
            ldsm4(b0, b1, b2, b3, bhBase + j * 8 * STRIDE + kc * 32);
            mma_f16(Dh[j],     a[4*kc+0], a[4*kc+1], a[4*kc+2], a[4*kc+3], b0, b1);
            mma_f16(Dh[j + 1], a[4*kc+0], a[4*kc+1], a[4*kc+2], a[4*kc+3], b2, b3);
            ldsm4(b0, b1, b2, b3, blBase + j * 8 * STRIDE + kc * 32);
            mma_f16(Dl[j],     a[4*kc+0], a[4*kc+1], a[4*kc+2], a[4*kc+3], b0, b1);
            mma_f16(Dl[j + 1], a[4*kc+0], a[4*kc+1], a[4*kc+2], a[4*kc+3], b2, b3);
        }
    }
}

template<int NJ>
__device__ __forceinline__ void init_acc(float Dh[][4], float Dl[][4],
                                         const char* sB, int tq) {
    #pragma unroll
    for (int j = 0; j < NJ; j++) {
        float2 b = *(const float2*)(sB + (8 * j + 2 * tq) * 4);
        Dh[j][0] = b.x; Dh[j][1] = b.y; Dh[j][2] = b.x; Dh[j][3] = b.y;
        Dl[j][0] = 0.f; Dl[j][1] = 0.f; Dl[j][2] = 0.f; Dl[j][3] = 0.f;
    }
}

// combine + tanh + fp16 pack -> store own cols into h tile (conflict-free)
template<int NJ>
__device__ __forceinline__ void epi_store_h(float Dh[][4], float Dl[][4],
                                            char* htile, int g, int tq,
                                            int colBase) {
    #pragma unroll
    for (int j = 0; j < NJ; j++) {
        float v0 = fast_tanh(fmaf(Dl[j][0], INV2048, Dh[j][0]));
        float v1 = fast_tanh(fmaf(Dl[j][1], INV2048, Dh[j][1]));
        float v2 = fast_tanh(fmaf(Dl[j][2], INV2048, Dh[j][2]));
        float v3 = fast_tanh(fmaf(Dl[j][3], INV2048, Dh[j][3]));
        int colB = (colBase + 8 * j + 2 * tq) * 2;
        *(uint32_t*)(htile + g * S_H + colB)       = packh2(v0, v1);
        *(uint32_t*)(htile + (g + 8) * S_H + colB) = packh2(v2, v3);
    }
}

// ---------------------------------------------------------------------------
// Phase B: fp16 2-pass mma.sync ODE scan, N-split warp pairs (R11 structure).
// 128 CTAs x 128 threads (2 pairs x 16 rows). Warp computes output cols
// [64*half, 64*half+64) (GEMM3: 32). Activations single fp16 (RN); weights
// exact via fp16 hi + 2048-scaled lo into separate accumulators.
// ---------------------------------------------------------------------------
__global__ __launch_bounds__(128, 1) void ode_mma_kernel(
    const float* __restrict__ oW1, const float* __restrict__ ob1,
    const float* __restrict__ oW2, const float* __restrict__ ob2,
    const float* __restrict__ oW3, const float* __restrict__ ob3,
    const float* __restrict__ decW, const float* __restrict__ decB,
    float* __restrict__ outPd, float* __restrict__ outSl)
{
    extern __shared__ char smraw[];
    uint32_t sb0 = smem_u32(smraw);
    uint32_t sbase = (sb0 + 1023) & ~1023u;
    char* sm = smraw + (sbase - sb0);
    const int tid = threadIdx.x;

    // ---- Fill transposed fp16 hi / scaled-lo weight tiles (one-time) ----
    for (int idx = tid; idx < ZD * OU; idx += 128) {           // W1 [64k][128n]
        int k = idx >> 7, n = idx & 127;
        float v = oW1[idx];
        __half hh = __float2half_rn(v);
        __half hl = __float2half_rn((v - __half2float(hh)) * 2048.0f);
        *(uint16_t*)(sm + OFF_W1H + n * S_W1 + k * 2) = __half_as_ushort(hh);
        *(uint16_t*)(sm + OFF_W1L + n * S_W1 + k * 2) = __half_as_ushort(hl);
    }
    for (int idx = tid; idx < OU * OU; idx += 128) {           // W2 [128][128]
        int k = idx >> 7, n = idx & 127;
        float v = oW2[idx];
        __half hh = __float2half_rn(v);
        __half hl = __float2half_rn((v - __half2float(hh)) * 2048.0f);
        *(uint16_t*)(sm + OFF_W2H + n * S_W2 + k * 2) = __half_as_ushort(hh);
        *(uint16_t*)(sm + OFF_W2L + n * S_W2 + k * 2) = __half_as_ushort(hl);
    }
    for (int idx = tid; idx < OU * ZD; idx += 128) {           // W3 [128k][64n]
        int k = idx >> 6, n = idx & 63;
        float v = oW3[idx];
        __half hh = __float2half_rn(v);
        __half hl = __float2half_rn((v - __half2float(hh)) * 2048.0f);
        *(uint16_t*)(sm + OFF_W3H + n * S_W3 + k * 2) = __half_as_ushort(hh);
        *(uint16_t*)(sm + OFF_W3L + n * S_W3 + k * 2) = __half_as_ushort(hl);
    }
    for (int i = tid; i < OU; i += 128) {
        ((float*)(sm + OFF_B1))[i] = ob1[i];
        ((float*)(sm + OFF_B2))[i] = ob2[i];
    }
    if (tid < ZD) {
        ((float*)(sm + OFF_B3))[tid] = ob3[tid];
        ((float*)(sm + OFF_D0))[tid] = decW[2 * tid];
        ((float*)(sm + OFF_D1))[tid] = decW[2 * tid + 1];
    }
    __syncthreads();

    const int wi = tid >> 5, l = tid & 31;
    const int half = wi & 1;                  // N-half within pair
    const int pairIdx = wi >> 1;
    const int base = blockIdx.x * 32 + pairIdx * 16;
    const int g = l >> 2, tq = l & 3;
    const int laneRow = l & 7, mi = l >> 3;

    // B-side ldmatrix lane addresses (layouts validated R9/R11)
    const int jo = mi >> 1, hf = mi & 1;
    const uint32_t aW1H = sbase + OFF_W1H + (uint32_t)((64 * half + jo * 8 + laneRow) * S_W1 + hf * 16);
    const uint32_t aW1L = aW1H + (uint32_t)(OFF_W1L - OFF_W1H);
    const uint32_t aW2H = sbase + OFF_W2H + (uint32_t)((64 * half + jo * 8 + laneRow) * S_W2 + hf * 16);
    const uint32_t aW2L = aW2H + (uint32_t)(OFF_W2L - OFF_W2H);
    const uint32_t aW3H = sbase + OFF_W3H + (uint32_t)((32 * half + jo * 8 + laneRow) * S_W3 + hf * 16);
    const uint32_t aW3L = aW3H + (uint32_t)(OFF_W3L - OFF_W3H);

    // A-side ldmatrix lane addresses into h tiles
    const uint32_t aoff = (uint32_t)((laneRow + 8 * (mi & 1)) * S_H + (mi >> 1) * 16);
    const uint32_t aH1 = sbase + OFF_H1 + (uint32_t)(pairIdx * H_GRP) + aoff;
    const uint32_t aH2 = sbase + OFF_H2 + (uint32_t)(pairIdx * H_GRP) + aoff;
    char* h1w = sm + OFF_H1 + pairIdx * H_GRP;
    char* h2w = sm + OFF_H2 + pairIdx * H_GRP;
    float* fbuf = (float*)(sm + OFF_XF);

    // fp32 z state (full 64 cols, replicated in pair), D-frag layout
    float z[8][4];
    #pragma unroll
    for (int j = 0; j < 8; j++) {
        float2 p = *(const float2*)(gZaug + (size_t)(base + g) * ZD + 8 * j + 2 * tq);
        float2 qv = *(const float2*)(gZaug + (size_t)(base + g + 8) * ZD + 8 * j + 2 * tq);
        z[j][0] = p.x; z[j][1] = p.y; z[j][2] = qv.x; z[j][3] = qv.y;
    }

    const float dt = 1.0f / (float)TN;
    const float db0 = decB[0], db1v = decB[1];
    const unsigned FULL = 0xffffffffu;

    for (int t = 0; t < TN; t++) {
        // ===== GEMM1: D = z @ W1 + b1 (K=64 -> own 64 cols) =====
        float Dh[8][4], Dl[8][4];
        init_acc<8>(Dh, Dl, sm + OFF_B1 + 64 * half * 4, tq);
        {
            uint32_t za[16];
            #pragma unroll
            for (int kc = 0; kc < 4; kc++) {
                za[4*kc+0] = packh2(z[2*kc][0],   z[2*kc][1]);
                za[4*kc+1] = packh2(z[2*kc][2],   z[2*kc][3]);
                za[4*kc+2] = packh2(z[2*kc+1][0], z[2*kc+1][1]);
                za[4*kc+3] = packh2(z[2*kc+1][2], z[2*kc+1][3]);
            }
            gemm2p_rA<4, 8, S_W1>(Dh, Dl, za, aW1H, aW1L);
        }
        epi_store_h<8>(Dh, Dl, h1w, g, tq, 64 * half);
        __syncthreads();

        // ===== GEMM2: D = h1 @ W2 + b2 (K=128 -> own 64 cols) =====
        init_acc<8>(Dh, Dl, sm + OFF_B2 + 64 * half * 4, tq);
        gemm2p_sA<8, 8, S_W2>(Dh, Dl, aH1, aW2H, aW2L);
        epi_store_h<8>(Dh, Dl, h2w, g, tq, 64 * half);
        __syncthreads();

        // ===== GEMM3: D3 = h2 @ W3 + b3 (K=128 -> own 32 cols) =====
        float D3h[4][4], D3l[4][4];
        init_acc<4>(D3h, D3l, sm + OFF_B3 + 32 * half * 4, tq);
        gemm2p_sA<8, 4, S_W3>(D3h, D3l, aH2, aW3H, aW3L);

        // combine lo correction into fp32 f values
        float D3[4][4];
        #pragma unroll
        for (int j = 0; j < 4; j++) {
            D3[j][0] = fmaf(D3l[j][0], INV2048, D3h[j][0]);
            D3[j][1] = fmaf(D3l[j][1], INV2048, D3h[j][1]);
            D3[j][2] = fmaf(D3l[j][2], INV2048, D3h[j][2]);
            D3[j][3] = fmaf(D3l[j][3], INV2048, D3h[j][3]);
        }

        // f exchange: transposed layout [i][tid] -> conflict-free
        #pragma unroll
        for (int j = 0; j < 4; j++) {
            fbuf[(4*j + 0) * 128 + tid] = D3[j][0];
            fbuf[(4*j + 1) * 128 + tid] = D3[j][1];
            fbuf[(4*j + 2) * 128 + tid] = D3[j][2];
            fbuf[(4*j + 3) * 128 + tid] = D3[j][3];
        }
        __syncthreads();
        const int ptid = tid ^ 32;

        // ===== z update (full, replicated), decode, store =====
        float pdA = 0.f, pdB = 0.f, slA = 0.f, slB = 0.f;
        #pragma unroll
        for (int j = 0; j < 8; j++) {
            float f0, f1, f2, f3;
            int jj = j & 3;
            if ((j >> 2) == half) {
                f0 = D3[jj][0]; f1 = D3[jj][1]; f2 = D3[jj][2]; f3 = D3[jj][3];
            } else {
                f0 = fbuf[(4*jj + 0) * 128 + ptid];
                f1 = fbuf[(4*jj + 1) * 128 + ptid];
                f2 = fbuf[(4*jj + 2) * 128 + ptid];
                f3 = fbuf[(4*jj + 3) * 128 + ptid];
            }
            z[j][0] = fmaf(dt, f0, z[j][0]);
            z[j][1] = fmaf(dt, f1, z[j][1]);
            z[j][2] = fmaf(dt, f2, z[j][2]);
            z[j][3] = fmaf(dt, f3, z[j][3]);
            float2 d0 = *(const float2*)(sm + OFF_D0 + (8 * j + 2 * tq) * 4);
            float2 d1 = *(const float2*)(sm + OFF_D1 + (8 * j + 2 * tq) * 4);
            pdA += z[j][0] * d0.x + z[j][1] * d0.y;
            pdB += z[j][2] * d0.x + z[j][3] * d0.y;
            slA += z[j][0] * d1.x + z[j][1] * d1.y;
            slB += z[j][2] * d1.x + z[j][3] * d1.y;
        }
        pdA += __shfl_xor_sync(FULL, pdA, 1); pdA += __shfl_xor_sync(FULL, pdA, 2);
        pdB += __shfl_xor_sync(FULL, pdB, 1); pdB += __shfl_xor_sync(FULL, pdB, 2);
        slA += __shfl_xor_sync(FULL, slA, 1); slA += __shfl_xor_sync(FULL, slA, 2);
        slB += __shfl_xor_sync(FULL, slB, 1); slB += __shfl_xor_sync(FULL, slB, 2);
        if (half == 0 && tq == 0) {
            size_t r0 = (size_t)(base + g), r1 = r0 + 8;
            outPd[r0 * TOUT + t + 1] = pdA + db0;
            outSl[r0 * TOUT + t + 1] = slA + db1v;
            outPd[r1 * TOUT + t + 1] = pdB + db0;
            outSl[r1 * TOUT + t + 1] = slB + db1v;
        }
    }
}

// ---------------------------------------------------------------------------
// Launch
// ---------------------------------------------------------------------------
extern "C" void kernel_launch(void* const* d_in, const int* in_sizes, int n_in,
                              void* d_out, int out_size)
{
    const float* bert  = (const float*)d_in[0];
    const float* eps   = (const float*)d_in[3];
    const float* projW = (const float*)d_in[4];
    const float* projB = (const float*)d_in[5];
    const float* lnG   = (const float*)d_in[6];
    const float* lnB   = (const float*)d_in[7];
    const float* lns   = (const float*)d_in[8];
    const float* dW1   = (const float*)d_in[9];
    const float* db1   = (const float*)d_in[10];
    const float* dW2   = (const float*)d_in[11];
    const float* db2   = (const float*)d_in[12];
    const float* oW1   = (const float*)d_in[13];
    const float* ob1   = (const float*)d_in[14];
    const float* oW2   = (const float*)d_in[15];
    const float* ob2   = (const float*)d_in[16];
    const float* oW3   = (const float*)d_in[17];
    const float* ob3   = (const float*)d_in[18];
    const float* decW  = (const float*)d_in[19];
    const float* decB  = (const float*)d_in[20];

    float* out    = (float*)d_out;
    float* outPd  = out;
    float* outSl  = out + (size_t)BN * TOUT;
    float* outDif = out + 2 * (size_t)BN * TOUT;

    phaseA_kernel<<<512, 256>>>(bert, eps, projW, projB, lnG, lnB, lns,
                                dW1, db1, dW2, db2, decW, decB, outPd, outSl);
    reduceDiff_kernel<<<1, 256>>>(outDif);

    int smemBytes = 1024 + SMEM_USED;
    cudaFuncSetAttribute(ode_mma_kernel, cudaFuncAttributeMaxDynamicSharedMemorySize,
                         smemBytes);
    ode_mma_kernel<<<BN / 32, 128, smemBytes>>>(oW1, ob1, oW2, ob2, oW3, ob3,
                                                decW, decB, outPd, outSl);
}

// round 17
// speedup vs baseline: 1.9391x; 1.4064x over previous
#include <cuda_runtime.h>
#include <cuda_fp16.h>
#include <math.h>
#include <stdint.h>

// Problem constants
#define BN   4096
#define TN   512
#define ZD   64
#define OU   128
#define BERT 768
#define TOUT 513

// Scratch (device globals: no allocation allowed)
__device__ float gZaug[BN * ZD];
__device__ float gPartial[BN];

// tanh(x) = 1 - 2/(exp2(2x*log2e)+1). HW-validated (R3/R6/R9/R11/R15).
__device__ __forceinline__ float fast_tanh(float x) {
    float e;
    asm("ex2.approx.f32 %0, %1;" : "=f"(e) : "f"(x * 2.8853900817779268f));
    return 1.0f - __fdividef(2.0f, e + 1.0f);
}

__device__ __forceinline__ uint32_t smem_u32(const void* p) {
    uint32_t a;
    asm("{ .reg .u64 t; cvta.to.shared.u64 t, %1; cvt.u32.u64 %0, t; }"
        : "=r"(a) : "l"(p));
    return a;
}

__device__ __forceinline__ void ldsm4(uint32_t& r0, uint32_t& r1,
                                      uint32_t& r2, uint32_t& r3, uint32_t addr) {
    asm volatile("ldmatrix.sync.aligned.m8n8.x4.shared.b16 {%0,%1,%2,%3}, [%4];"
                 : "=r"(r0), "=r"(r1), "=r"(r2), "=r"(r3) : "r"(addr));
}

__device__ __forceinline__ void mma_f16(float c[4], uint32_t a0, uint32_t a1,
                                        uint32_t a2, uint32_t a3,
                                        uint32_t b0, uint32_t b1) {
    asm volatile("mma.sync.aligned.m16n8k16.row.col.f32.f16.f16.f32 "
                 "{%0,%1,%2,%3}, {%4,%5,%6,%7}, {%8,%9}, {%0,%1,%2,%3};"
                 : "+f"(c[0]), "+f"(c[1]), "+f"(c[2]), "+f"(c[3])
                 : "r"(a0), "r"(a1), "r"(a2), "r"(a3), "r"(b0), "r"(b1));
}

// pack two fp32 -> fp16x2 (v0 low, v1 high), round-to-nearest
__device__ __forceinline__ uint32_t packh2(float v0, float v1) {
    uint32_t r;
    asm("cvt.rn.f16x2.f32 %0, %1, %2;" : "=r"(r) : "f"(v1), "f"(v0));
    return r;
}

// ---------------------------------------------------------------------------
// Phase A: warp-per-row (unchanged, validated ~110us)
// ---------------------------------------------------------------------------
__global__ __launch_bounds__(256) void phaseA_kernel(
    const float* __restrict__ bert, const float* __restrict__ eps,
    const float* __restrict__ projW, const float* __restrict__ projB,
    const float* __restrict__ lnG, const float* __restrict__ lnB,
    const float* __restrict__ lns,
    const float* __restrict__ dW1, const float* __restrict__ db1,
    const float* __restrict__ dW2, const float* __restrict__ db2,
    const float* __restrict__ decW, const float* __restrict__ decB,
    float* __restrict__ outPd, float* __restrict__ outSl)
{
    const unsigned FULL = 0xffffffffu;
    int warp = (blockIdx.x * blockDim.x + threadIdx.x) >> 5;
    int l = threadIdx.x & 31;
    if (warp >= BN) return;
    const int r = warp;
    const int c = 2 * l;

    const float* brow = bert + (size_t)r * BERT;
    float hx = 0.f, hy = 0.f;
    #pragma unroll 4
    for (int k = 0; k < BERT; k++) {
        float bv = __ldg(brow + k);
        float2 wv = *(const float2*)(projW + k * ZD + c);
        hx = fmaf(bv, wv.x, hx);
        hy = fmaf(bv, wv.y, hy);
    }
    hx += projB[c]; hy += projB[c + 1];

    float s = hx + hy;
    #pragma unroll
    for (int o = 16; o; o >>= 1) s += __shfl_xor_sync(FULL, s, o);
    float mu = s * (1.0f / 64.0f);
    float d0 = hx - mu, d1 = hy - mu;
    float ss = d0 * d0 + d1 * d1;
    #pragma unroll
    for (int o = 16; o; o >>= 1) ss += __shfl_xor_sync(FULL, ss, o);
    float var = ss * (1.0f / 64.0f);
    float rs = rsqrtf(var + 1e-5f);
    float zc0 = d0 * rs * lnG[c]     + lnB[c];
    float zc1 = d1 * rs * lnG[c + 1] + lnB[c + 1];

    float sigma = log1pf(expf(lns[0]));
    float zn0 = zc0 + sigma * eps[(size_t)r * ZD + c];
    float zn1 = zc1 + sigma * eps[(size_t)r * ZD + c + 1];

    int j0 = 4 * l;
    float4 a = *(const float4*)(db1 + j0);
    #pragma unroll 4
    for (int k2 = 0; k2 < 32; k2++) {
        float zva = __shfl_sync(FULL, zn0, k2);
        float zvb = __shfl_sync(FULL, zn1, k2);
        int k = 2 * k2;
        float4 w = *(const float4*)(dW1 + k * OU + j0);
        a.x = fmaf(zva, w.x, a.x); a.y = fmaf(zva, w.y, a.y);
        a.z = fmaf(zva, w.z, a.z); a.w = fmaf(zva, w.w, a.w);
        w = *(const float4*)(dW1 + (k + 1) * OU + j0);
        a.x = fmaf(zvb, w.x, a.x); a.y = fmaf(zvb, w.y, a.y);
        a.z = fmaf(zvb, w.z, a.z); a.w = fmaf(zvb, w.w, a.w);
    }
    a.x = a.x / (1.f + expf(-a.x));
    a.y = a.y / (1.f + expf(-a.y));
    a.z = a.z / (1.f + expf(-a.z));
    a.w = a.w / (1.f + expf(-a.w));

    float za0 = db2[c], za1 = db2[c + 1];
    float a1v[4] = {a.x, a.y, a.z, a.w};
    #pragma unroll 2
    for (int k4 = 0; k4 < 32; k4++) {
        #pragma unroll
        for (int j = 0; j < 4; j++) {
            float hv = __shfl_sync(FULL, a1v[j], k4);
            int k = 4 * k4 + j;
            float2 w = *(const float2*)(dW2 + k * ZD + c);
            za0 = fmaf(hv, w.x, za0);
            za1 = fmaf(hv, w.y, za1);
        }
    }

    float dd = (za0 - zc0) * (za0 - zc0) + (za1 - zc1) * (za1 - zc1);
    #pragma unroll
    for (int o = 16; o; o >>= 1) dd += __shfl_xor_sync(FULL, dd, o);
    if (l == 0) gPartial[r] = dd;

    *(float2*)(gZaug + (size_t)r * ZD + c) = make_float2(za0, za1);

    float pd = za0 * decW[c * 2 + 0] + za1 * decW[(c + 1) * 2 + 0];
    float sl = za0 * decW[c * 2 + 1] + za1 * decW[(c + 1) * 2 + 1];
    #pragma unroll
    for (int o = 16; o; o >>= 1) {
        pd += __shfl_xor_sync(FULL, pd, o);
        sl += __shfl_xor_sync(FULL, sl, o);
    }
    if (l == 0) {
        outPd[(size_t)r * TOUT] = pd + decB[0];
        outSl[(size_t)r * TOUT] = sl + decB[1];
    }
}

__global__ void reduceDiff_kernel(float* __restrict__ outDiff)
{
    __shared__ float sh[256];
    float s = 0.f;
    for (int i = threadIdx.x; i < BN; i += 256) s += gPartial[i];
    sh[threadIdx.x] = s;
    __syncthreads();
    for (int step = 128; step; step >>= 1) {
        if (threadIdx.x < step) sh[threadIdx.x] += sh[threadIdx.x + step];
        __syncthreads();
    }
    if (threadIdx.x == 0) outDiff[0] = sh[0] * (1.0f / ((float)BN * (float)ZD));
}

// ---------------------------------------------------------------------------
// SMEM layout. Weights single fp16 (RN), transposed n-major, +16B pad.
// h tiles: fp16, [16 rows][128], stride 272B, per 16-row pair.
// ---------------------------------------------------------------------------
#define S_W1 144
#define S_W2 272
#define S_W3 272
#define S_H  272
#define H_GRP 4352
#define OFF_W1  0
#define OFF_W2  (OFF_W1 + 128 * S_W1)          // 18432
#define OFF_W3  (OFF_W2 + 128 * S_W2)          // 53248
#define OFF_B1  (OFF_W3 + 64 * S_W3)           // 70656
#define OFF_B2  (OFF_B1 + 512)
#define OFF_B3  (OFF_B2 + 512)
#define OFF_D0  (OFF_B3 + 256)
#define OFF_D1  (OFF_D0 + 256)
#define OFF_H1  (OFF_D1 + 256)                 // 72448: 2 pairs x 4352
#define OFF_H2  (OFF_H1 + 2 * H_GRP)           // 81152
#define OFF_XF  (OFF_H2 + 2 * H_GRP)           // 89856: f [16][128] f32
#define SMEM_USED (OFF_XF + 8192)              // 98048

// single-pass GEMM, A from smem via ldmatrix
template<int NKC, int NJ, int STRIDE>
__device__ __forceinline__ void gemm1p_sA(float D[][4], uint32_t aBase,
                                          uint32_t bBase) {
    #pragma unroll
    for (int kc = 0; kc < NKC; kc++) {
        uint32_t a0, a1, a2, a3;
        ldsm4(a0, a1, a2, a3, aBase + kc * 32);
        #pragma unroll
        for (int j = 0; j < NJ; j += 2) {
            uint32_t b0, b1, b2, b3;
            ldsm4(b0, b1, b2, b3, bBase + j * 8 * STRIDE + kc * 32);
            mma_f16(D[j],     a0, a1, a2, a3, b0, b1);
            mma_f16(D[j + 1], a0, a1, a2, a3, b2, b3);
        }
    }
}

// single-pass GEMM, A from registers (GEMM1: z fragments)
template<int NKC, int NJ, int STRIDE>
__device__ __forceinline__ void gemm1p_rA(float D[][4], const uint32_t* a,
                                          uint32_t bBase) {
    #pragma unroll
    for (int kc = 0; kc < NKC; kc++) {
        #pragma unroll
        for (int j = 0; j < NJ; j += 2) {
            uint32_t b0, b1, b2, b3;
            ldsm4(b0, b1, b2, b3, bBase + j * 8 * STRIDE + kc * 32);
            mma_f16(D[j],     a[4*kc+0], a[4*kc+1], a[4*kc+2], a[4*kc+3], b0, b1);
            mma_f16(D[j + 1], a[4*kc+0], a[4*kc+1], a[4*kc+2], a[4*kc+3], b2, b3);
        }
    }
}

template<int NJ>
__device__ __forceinline__ void init_bias(float D[][4], const char* sB, int tq) {
    #pragma unroll
    for (int j = 0; j < NJ; j++) {
        float2 b = *(const float2*)(sB + (8 * j + 2 * tq) * 4);
        D[j][0] = b.x; D[j][1] = b.y; D[j][2] = b.x; D[j][3] = b.y;
    }
}

// tanh + fp16 pack -> store own cols into h tile (conflict-free)
template<int NJ>
__device__ __forceinline__ void epi_store_h(float D[][4], char* htile,
                                            int g, int tq, int colBase) {
    #pragma unroll
    for (int j = 0; j < NJ; j++) {
        float v0 = fast_tanh(D[j][0]);
        float v1 = fast_tanh(D[j][1]);
        float v2 = fast_tanh(D[j][2]);
        float v3 = fast_tanh(D[j][3]);
        int colB = (colBase + 8 * j + 2 * tq) * 2;
        *(uint32_t*)(htile + g * S_H + colB)       = packh2(v0, v1);
        *(uint32_t*)(htile + (g + 8) * S_H + colB) = packh2(v2, v3);
    }
}

// ---------------------------------------------------------------------------
// Phase B: single-pass fp16 mma.sync ODE scan, N-split warp pairs.
// 128 CTAs x 128 threads (2 pairs x 16 rows). Warp computes output cols
// [64*half, 64*half+64) (GEMM3: 32). z fp32, replicated in pair.
// ---------------------------------------------------------------------------
__global__ __launch_bounds__(128, 1) void ode_mma_kernel(
    const float* __restrict__ oW1, const float* __restrict__ ob1,
    const float* __restrict__ oW2, const float* __restrict__ ob2,
    const float* __restrict__ oW3, const float* __restrict__ ob3,
    const float* __restrict__ decW, const float* __restrict__ decB,
    float* __restrict__ outPd, float* __restrict__ outSl)
{
    extern __shared__ char smraw[];
    uint32_t sb0 = smem_u32(smraw);
    uint32_t sbase = (sb0 + 1023) & ~1023u;
    char* sm = smraw + (sbase - sb0);
    const int tid = threadIdx.x;

    // ---- Fill transposed fp16 weight tiles (one-time) ----
    for (int idx = tid; idx < ZD * OU; idx += 128) {           // W1 [64k][128n]
        int k = idx >> 7, n = idx & 127;
        *(uint16_t*)(sm + OFF_W1 + n * S_W1 + k * 2) =
            __half_as_ushort(__float2half_rn(oW1[idx]));
    }
    for (int idx = tid; idx < OU * OU; idx += 128) {           // W2 [128][128]
        int k = idx >> 7, n = idx & 127;
        *(uint16_t*)(sm + OFF_W2 + n * S_W2 + k * 2) =
            __half_as_ushort(__float2half_rn(oW2[idx]));
    }
    for (int idx = tid; idx < OU * ZD; idx += 128) {           // W3 [128k][64n]
        int k = idx >> 6, n = idx & 63;
        *(uint16_t*)(sm + OFF_W3 + n * S_W3 + k * 2) =
            __half_as_ushort(__float2half_rn(oW3[idx]));
    }
    for (int i = tid; i < OU; i += 128) {
        ((float*)(sm + OFF_B1))[i] = ob1[i];
        ((float*)(sm + OFF_B2))[i] = ob2[i];
    }
    if (tid < ZD) {
        ((float*)(sm + OFF_B3))[tid] = ob3[tid];
        ((float*)(sm + OFF_D0))[tid] = decW[2 * tid];
        ((float*)(sm + OFF_D1))[tid] = decW[2 * tid + 1];
    }
    __syncthreads();

    const int wi = tid >> 5, l = tid & 31;
    const int half = wi & 1;                  // N-half within pair
    const int pairIdx = wi >> 1;
    const int base = blockIdx.x * 32 + pairIdx * 16;
    const int g = l >> 2, tq = l & 3;
    const int laneRow = l & 7, mi = l >> 3;

    // B-side ldmatrix lane addresses (layouts validated R9/R11/R15)
    const int jo = mi >> 1, hf = mi & 1;
    const uint32_t aW1 = sbase + OFF_W1 + (uint32_t)((64 * half + jo * 8 + laneRow) * S_W1 + hf * 16);
    const uint32_t aW2 = sbase + OFF_W2 + (uint32_t)((64 * half + jo * 8 + laneRow) * S_W2 + hf * 16);
    const uint32_t aW3 = sbase + OFF_W3 + (uint32_t)((32 * half + jo * 8 + laneRow) * S_W3 + hf * 16);

    // A-side ldmatrix lane addresses into h tiles
    const uint32_t aoff = (uint32_t)((laneRow + 8 * (mi & 1)) * S_H + (mi >> 1) * 16);
    const uint32_t aH1 = sbase + OFF_H1 + (uint32_t)(pairIdx * H_GRP) + aoff;
    const uint32_t aH2 = sbase + OFF_H2 + (uint32_t)(pairIdx * H_GRP) + aoff;
    char* h1w = sm + OFF_H1 + pairIdx * H_GRP;
    char* h2w = sm + OFF_H2 + pairIdx * H_GRP;
    float* fbuf = (float*)(sm + OFF_XF);

    // fp32 z state (full 64 cols, replicated in pair), D-frag layout
    float z[8][4];
    #pragma unroll
    for (int j = 0; j < 8; j++) {
        float2 p = *(const float2*)(gZaug + (size_t)(base + g) * ZD + 8 * j + 2 * tq);
        float2 qv = *(const float2*)(gZaug + (size_t)(base + g + 8) * ZD + 8 * j + 2 * tq);
        z[j][0] = p.x; z[j][1] = p.y; z[j][2] = qv.x; z[j][3] = qv.y;
    }

    const float dt = 1.0f / (float)TN;
    const float db0 = decB[0], db1v = decB[1];
    const unsigned FULL = 0xffffffffu;

    for (int t = 0; t < TN; t++) {
        // ===== GEMM1: D = z @ W1 + b1 (K=64 -> own 64 cols) =====
        float D[8][4];
        init_bias<8>(D, sm + OFF_B1 + 64 * half * 4, tq);
        {
            uint32_t za[16];
            #pragma unroll
            for (int kc = 0; kc < 4; kc++) {
                za[4*kc+0] = packh2(z[2*kc][0],   z[2*kc][1]);
                za[4*kc+1] = packh2(z[2*kc][2],   z[2*kc][3]);
                za[4*kc+2] = packh2(z[2*kc+1][0], z[2*kc+1][1]);
                za[4*kc+3] = packh2(z[2*kc+1][2], z[2*kc+1][3]);
            }
            gemm1p_rA<4, 8, S_W1>(D, za, aW1);
        }
        epi_store_h<8>(D, h1w, g, tq, 64 * half);
        __syncthreads();

        // ===== GEMM2: D = h1 @ W2 + b2 (K=128 -> own 64 cols) =====
        init_bias<8>(D, sm + OFF_B2 + 64 * half * 4, tq);
        gemm1p_sA<8, 8, S_W2>(D, aH1, aW2);
        epi_store_h<8>(D, h2w, g, tq, 64 * half);
        __syncthreads();

        // ===== GEMM3: D3 = h2 @ W3 + b3 (K=128 -> own 32 cols) =====
        float D3[4][4];
        init_bias<4>(D3, sm + OFF_B3 + 32 * half * 4, tq);
        gemm1p_sA<8, 4, S_W3>(D3, aH2, aW3);

        // f exchange: transposed layout [i][tid] -> conflict-free
        #pragma unroll
        for (int j = 0; j < 4; j++) {
            fbuf[(4*j + 0) * 128 + tid] = D3[j][0];
            fbuf[(4*j + 1) * 128 + tid] = D3[j][1];
            fbuf[(4*j + 2) * 128 + tid] = D3[j][2];
            fbuf[(4*j + 3) * 128 + tid] = D3[j][3];
        }
        __syncthreads();
        const int ptid = tid ^ 32;

        // ===== z update (full, replicated), decode, store =====
        float pdA = 0.f, pdB = 0.f, slA = 0.f, slB = 0.f;
        #pragma unroll
        for (int j = 0; j < 8; j++) {
            float f0, f1, f2, f3;
            int jj = j & 3;
            if ((j >> 2) == half) {
                f0 = D3[jj][0]; f1 = D3[jj][1]; f2 = D3[jj][2]; f3 = D3[jj][3];
            } else {
                f0 = fbuf[(4*jj + 0) * 128 + ptid];
                f1 = fbuf[(4*jj + 1) * 128 + ptid];
                f2 = fbuf[(4*jj + 2) * 128 + ptid];
                f3 = fbuf[(4*jj + 3) * 128 + ptid];
            }
            z[j][0] = fmaf(dt, f0, z[j][0]);
            z[j][1] = fmaf(dt, f1, z[j][1]);
            z[j][2] = fmaf(dt, f2, z[j][2]);
            z[j][3] = fmaf(dt, f3, z[j][3]);
            float2 d0 = *(const float2*)(sm + OFF_D0 + (8 * j + 2 * tq) * 4);
            float2 d1 = *(const float2*)(sm + OFF_D1 + (8 * j + 2 * tq) * 4);
            pdA += z[j][0] * d0.x + z[j][1] * d0.y;
            pdB += z[j][2] * d0.x + z[j][3] * d0.y;
            slA += z[j][0] * d1.x + z[j][1] * d1.y;
            slB += z[j][2] * d1.x + z[j][3] * d1.y;
        }
        pdA += __shfl_xor_sync(FULL, pdA, 1); pdA += __shfl_xor_sync(FULL, pdA, 2);
        pdB += __shfl_xor_sync(FULL, pdB, 1); pdB += __shfl_xor_sync(FULL, pdB, 2);
        slA += __shfl_xor_sync(FULL, slA, 1); slA += __shfl_xor_sync(FULL, slA, 2);
        slB += __shfl_xor_sync(FULL, slB, 1); slB += __shfl_xor_sync(FULL, slB, 2);
        if (half == 0 && tq == 0) {
            size_t r0 = (size_t)(base + g), r1 = r0 + 8;
            outPd[r0 * TOUT + t + 1] = pdA + db0;
            outSl[r0 * TOUT + t + 1] = slA + db1v;
            outPd[r1 * TOUT + t + 1] = pdB + db0;
            outSl[r1 * TOUT + t + 1] = slB + db1v;
        }
    }
}

// ---------------------------------------------------------------------------
// Launch
// ---------------------------------------------------------------------------
extern "C" void kernel_launch(void* const* d_in, const int* in_sizes, int n_in,
                              void* d_out, int out_size)
{
    const float* bert  = (const float*)d_in[0];
    const float* eps   = (const float*)d_in[3];
    const float* projW = (const float*)d_in[4];
    const float* projB = (const float*)d_in[5];
    const float* lnG   = (const float*)d_in[6];
    const float* lnB   = (const float*)d_in[7];
    const float* lns   = (const float*)d_in[8];
    const float* dW1   = (const float*)d_in[9];
    const float* db1   = (const float*)d_in[10];
    const float* dW2   = (const float*)d_in[11];
    const float* db2   = (const float*)d_in[12];
    const float* oW1   = (const float*)d_in[13];
    const float* ob1   = (const float*)d_in[14];
    const float* oW2   = (const float*)d_in[15];
    const float* ob2   = (const float*)d_in[16];
    const float* oW3   = (const float*)d_in[17];
    const float* ob3   = (const float*)d_in[18];
    const float* decW  = (const float*)d_in[19];
    const float* decB  = (const float*)d_in[20];

    float* out    = (float*)d_out;
    float* outPd  = out;
    float* outSl  = out + (size_t)BN * TOUT;
    float* outDif = out + 2 * (size_t)BN * TOUT;

    phaseA_kernel<<<512, 256>>>(bert, eps, projW, projB, lnG, lnB, lns,
                                dW1, db1, dW2, db2, decW, decB, outPd, outSl);
    reduceDiff_kernel<<<1, 256>>>(outDif);

    int smemBytes = 1024 + SMEM_USED;
    cudaFuncSetAttribute(ode_mma_kernel, cudaFuncAttributeMaxDynamicSharedMemorySize,
                         smemBytes);
    ode_mma_kernel<<<BN / 32, 128, smemBytes>>>(oW1, ob1, oW2, ob2, oW3, ob3,
                                                decW, decB, outPd, outSl);
}